// round 9
// baseline (speedup 1.0000x reference)
#include <cuda_runtime.h>
#include <math.h>

#define IN_CH 128
#define HID 64
#define NMAX 50000
#define EMAX 800000

// Scratch (__device__ globals; no allocation allowed)
__device__ float g_deg[NMAX];              // degree, then dinv in place
__device__ float g_h[NMAX * HID];          // h' = (X@W) * dinv[row]  (gather source)
__device__ float g_agg1[NMAX * HID];       // layer-1 aggregation (init = h' via dual-store)
__device__ float g_agg2[NMAX * HID];       // layer-2 aggregation

// ---------------------------------------------------------------------------
__global__ void init_deg_kernel(int n) {
    int i = blockIdx.x * blockDim.x + threadIdx.x;
    if (i < n) g_deg[i] = 1.0f;            // self-loop contributes 1
}

__global__ void degree_kernel(const int* __restrict__ dst, int e) {
    int i = blockIdx.x * blockDim.x + threadIdx.x;
    if (i < e) {
        float* p = &g_deg[__ldg(dst + i)];
        asm volatile("red.global.add.f32 [%0], %1;" :: "l"(p), "f"(1.0f) : "memory");
    }
}

__global__ void dinv_kernel(int n) {
    int i = blockIdx.x * blockDim.x + threadIdx.x;
    if (i < n) g_deg[i] = rsqrtf(g_deg[i]);
}

// ---------------------------------------------------------------------------
// GEMM: out[i][c] = dinv[i] * sum_k in[i][k] * W[k][c], dual-stored to H and AGG.
// TRANS: input transform z = relu(dinv[i]*in[i][k] + bIn[k])  (layer-2 input)
// 256 threads -> 64 nodes x 64 cols. SINGLE-SHOT PREFETCH: each thread issues
// its entire X slice (K/4 floats = K/16 float4) in one batch (high MLP, one
// DRAM round trip), W streams to smem from L2 concurrently, then ONE sync and
// the whole K-loop runs from smem (pure LDS + FFMA2, no staging stalls).
// Thread (tx,ty): cols {4tx..+4, 4tx+32..+4}, nodes {2ty, 2ty+1}.
template <int K, bool TRANS>
__global__ void __launch_bounds__(256, 2)
gemm_kernel(const float* __restrict__ X, const float* __restrict__ W,
            const float* __restrict__ bIn,
            float* __restrict__ H, float* __restrict__ AGG, int n) {
    constexpr int XP = K + 4;              // Xs pitch (conflict-free reads)
    constexpr int NG = K / 16;             // float4s per thread's X slice
    __shared__ float Ws[K * HID];
    __shared__ float Xs[64 * XP];
    const int t = threadIdx.x;
    const int node0 = blockIdx.x * 64;

    // ---- X prefetch: 4 threads per row, each owns K/4 consecutive floats
    const int xr = t >> 2;                 // row 0..63
    const int xq = (t & 3) * (K / 4);      // col offset of this thread's slice
    const int xnode = node0 + xr;
    const bool xok = xnode < n;

    float4 xv[NG];
#pragma unroll
    for (int g = 0; g < NG; ++g)
        xv[g] = xok ? *(const float4*)(X + xnode * K + xq + g * 4)
                    : make_float4(0.f, 0.f, 0.f, 0.f);

    // ---- W fill (L2-hot after first block) overlaps the X round trip
#pragma unroll
    for (int i = 0; i < K * HID / 1024; ++i)
        *(float4*)(Ws + i * 1024 + t * 4) = *(const float4*)(W + i * 1024 + t * 4);

    // ---- transform (layer-2 path) + store X slice to smem
    if (TRANS && xok) {
        float di = g_deg[xnode];
#pragma unroll
        for (int g = 0; g < NG; ++g) {
            float4 bb = *(const float4*)(bIn + xq + g * 4);
            xv[g].x = fmaxf(fmaf(di, xv[g].x, bb.x), 0.f);
            xv[g].y = fmaxf(fmaf(di, xv[g].y, bb.y), 0.f);
            xv[g].z = fmaxf(fmaf(di, xv[g].z, bb.z), 0.f);
            xv[g].w = fmaxf(fmaf(di, xv[g].w, bb.w), 0.f);
        }
    }
#pragma unroll
    for (int g = 0; g < NG; ++g)
        *(float4*)(Xs + xr * XP + xq + g * 4) = xv[g];

    __syncthreads();

    // ---- compute
    const int tx = t & 7;
    const int ty = t >> 3;                 // 0..31
    const int cA = tx * 4;
    const int n0 = ty * 2;

    unsigned long long acc[2][4];
#pragma unroll
    for (int m = 0; m < 2; ++m)
#pragma unroll
        for (int p = 0; p < 4; ++p) acc[m][p] = 0ULL;

#pragma unroll 8
    for (int k = 0; k < K; ++k) {
        ulonglong2 wA = *(const ulonglong2*)(Ws + k * HID + cA);
        ulonglong2 wB = *(const ulonglong2*)(Ws + k * HID + cA + 32);
        float x0 = Xs[n0 * XP + k];
        float x1 = Xs[(n0 + 1) * XP + k];
        unsigned long long xx0, xx1;
        asm("mov.b64 %0, {%1, %1};" : "=l"(xx0) : "f"(x0));
        asm("mov.b64 %0, {%1, %1};" : "=l"(xx1) : "f"(x1));
        asm("fma.rn.f32x2 %0, %1, %2, %0;" : "+l"(acc[0][0]) : "l"(wA.x), "l"(xx0));
        asm("fma.rn.f32x2 %0, %1, %2, %0;" : "+l"(acc[0][1]) : "l"(wA.y), "l"(xx0));
        asm("fma.rn.f32x2 %0, %1, %2, %0;" : "+l"(acc[0][2]) : "l"(wB.x), "l"(xx0));
        asm("fma.rn.f32x2 %0, %1, %2, %0;" : "+l"(acc[0][3]) : "l"(wB.y), "l"(xx0));
        asm("fma.rn.f32x2 %0, %1, %2, %0;" : "+l"(acc[1][0]) : "l"(wA.x), "l"(xx1));
        asm("fma.rn.f32x2 %0, %1, %2, %0;" : "+l"(acc[1][1]) : "l"(wA.y), "l"(xx1));
        asm("fma.rn.f32x2 %0, %1, %2, %0;" : "+l"(acc[1][2]) : "l"(wB.x), "l"(xx1));
        asm("fma.rn.f32x2 %0, %1, %2, %0;" : "+l"(acc[1][3]) : "l"(wB.y), "l"(xx1));
    }

#pragma unroll
    for (int m = 0; m < 2; ++m) {
        int node = node0 + n0 + m;
        if (node < n) {
            float di = g_deg[node];
            float o[8];
            asm("mov.b64 {%0,%1}, %2;" : "=f"(o[0]), "=f"(o[1]) : "l"(acc[m][0]));
            asm("mov.b64 {%0,%1}, %2;" : "=f"(o[2]), "=f"(o[3]) : "l"(acc[m][1]));
            asm("mov.b64 {%0,%1}, %2;" : "=f"(o[4]), "=f"(o[5]) : "l"(acc[m][2]));
            asm("mov.b64 {%0,%1}, %2;" : "=f"(o[6]), "=f"(o[7]) : "l"(acc[m][3]));
            float4 r0 = make_float4(o[0] * di, o[1] * di, o[2] * di, o[3] * di);
            float4 r1 = make_float4(o[4] * di, o[5] * di, o[6] * di, o[7] * di);
            int off = node * HID + cA;
            *(float4*)(H + off) = r0;
            *(float4*)(H + off + 32) = r1;
            *(float4*)(AGG + off) = r0;    // self-loop init: agg starts at h'[node]
            *(float4*)(AGG + off + 32) = r1;
        }
    }
}

// ---------------------------------------------------------------------------
// aggregation: agg[dst] += h'[src]  (unweighted; norm folded into producer/consumer)
// 16 lanes per edge, one red.global.add.v4.f32 per lane.
__global__ void agg_kernel(const int* __restrict__ src, const int* __restrict__ dst,
                           const float* __restrict__ h, float* __restrict__ agg, int e) {
    int tid = blockIdx.x * blockDim.x + threadIdx.x;
    int edge = tid >> 4;
    int q = tid & 15;
    if (edge >= e) return;
    int s = __ldg(src + edge);
    int d = __ldg(dst + edge);
    float4 v = *(const float4*)(h + s * HID + q * 4);
    float* p = agg + d * HID + q * 4;
    asm volatile("red.global.add.v4.f32 [%0], {%1,%2,%3,%4};"
                 :: "l"(p), "f"(v.x), "f"(v.y), "f"(v.z), "f"(v.w) : "memory");
}

// ---------------------------------------------------------------------------
// decode: out[e] = dot(z[src], z[dst]), z = dinv*agg2 + b2 on the fly.
__global__ void decode_kernel(const int* __restrict__ src, const int* __restrict__ dst,
                              const float* __restrict__ agg, const float* __restrict__ b,
                              float* __restrict__ out, int e) {
    int tid = blockIdx.x * blockDim.x + threadIdx.x;
    int edge = tid >> 4;
    int q = tid & 15;
    if (edge >= e) return;
    int s = __ldg(src + edge);
    int d = __ldg(dst + edge);
    float ds = g_deg[s], dd = g_deg[d];
    float4 as = *(const float4*)(agg + s * HID + q * 4);
    float4 ad = *(const float4*)(agg + d * HID + q * 4);
    float4 bb = *(const float4*)(b + q * 4);
    float p;
    {
        float zs = fmaf(ds, as.x, bb.x), zd = fmaf(dd, ad.x, bb.x);
        p = zs * zd;
        zs = fmaf(ds, as.y, bb.y); zd = fmaf(dd, ad.y, bb.y); p = fmaf(zs, zd, p);
        zs = fmaf(ds, as.z, bb.z); zd = fmaf(dd, ad.z, bb.z); p = fmaf(zs, zd, p);
        zs = fmaf(ds, as.w, bb.w); zd = fmaf(dd, ad.w, bb.w); p = fmaf(zs, zd, p);
    }
    p += __shfl_xor_sync(0xffffffffu, p, 8);
    p += __shfl_xor_sync(0xffffffffu, p, 4);
    p += __shfl_xor_sync(0xffffffffu, p, 2);
    p += __shfl_xor_sync(0xffffffffu, p, 1);
    if (q == 0) out[edge] = p;
}

// ---------------------------------------------------------------------------
extern "C" void kernel_launch(void* const* d_in, const int* in_sizes, int n_in,
                              void* d_out, int out_size) {
    const float* x  = (const float*)d_in[0];   // [n, IN_CH]
    const int*   ei = (const int*)d_in[1];     // [2, e]
    const float* W1 = (const float*)d_in[2];
    const float* b1 = (const float*)d_in[3];
    const float* W2 = (const float*)d_in[4];
    const float* b2 = (const float*)d_in[5];
    float* out = (float*)d_out;                // [e]

    int n = in_sizes[0] / IN_CH;
    int e = in_sizes[1] / 2;
    const int* src = ei;
    const int* dst = ei + e;

    float *p_h, *p_agg1, *p_agg2;
    cudaGetSymbolAddress((void**)&p_h, g_h);
    cudaGetSymbolAddress((void**)&p_agg1, g_agg1);
    cudaGetSymbolAddress((void**)&p_agg2, g_agg2);

    const int T = 256;
    int eg = (e * 16 + T - 1) / T;             // 16 lanes per edge

    init_deg_kernel<<<(n + T - 1) / T, T>>>(n);
    degree_kernel<<<(e + T - 1) / T, T>>>(dst, e);
    dinv_kernel<<<(n + T - 1) / T, T>>>(n);

    // layer 1: h' = (X@W1)*dinv, dual-store (agg1 starts at self-loop term)
    gemm_kernel<IN_CH, false><<<(n + 63) / 64, T>>>(x, W1, nullptr, p_h, p_agg1, n);
    agg_kernel<<<eg, T>>>(src, dst, p_h, p_agg1, e);

    // layer 2: input z1 = relu(dinv*agg1 + b1) fused into GEMM load
    gemm_kernel<HID, true><<<(n + 63) / 64, T>>>(p_agg1, W2, b1, p_h, p_agg2, n);
    agg_kernel<<<eg, T>>>(src, dst, p_h, p_agg2, e);

    // decode (z2 = dinv*agg2 + b2 folded)
    decode_kernel<<<eg, T>>>(src, dst, p_agg2, b2, out, e);
}

// round 10
// speedup vs baseline: 1.1067x; 1.1067x over previous
#include <cuda_runtime.h>
#include <math.h>

#define IN_CH 128
#define HID 64
#define NMAX 50000
#define EMAX 800000

// Scratch (__device__ globals; no allocation allowed)
__device__ float g_deg[NMAX];              // degree, then dinv in place
__device__ float g_h[NMAX * HID];          // h' = (X@W) * dinv[row]  (gather source)
__device__ float g_agg1[NMAX * HID];       // layer-1 aggregation (init = h' via dual-store)
__device__ float g_agg2[NMAX * HID];       // layer-2 aggregation

// ---------------------------------------------------------------------------
__global__ void init_deg_kernel(int n) {
    int i = blockIdx.x * blockDim.x + threadIdx.x;
    if (i < n) g_deg[i] = 1.0f;            // self-loop contributes 1
}

__global__ void degree_kernel(const int* __restrict__ dst, int e) {
    int i = blockIdx.x * blockDim.x + threadIdx.x;
    if (i < e) {
        float* p = &g_deg[__ldg(dst + i)];
        asm volatile("red.global.add.f32 [%0], %1;" :: "l"(p), "f"(1.0f) : "memory");
    }
}

__global__ void dinv_kernel(int n) {
    int i = blockIdx.x * blockDim.x + threadIdx.x;
    if (i < n) g_deg[i] = rsqrtf(g_deg[i]);
}

// ---------------------------------------------------------------------------
// GEMM: out[i][c] = dinv[i] * sum_k in[i][k] * W[k][c], dual-stored to H and AGG.
// TRANS: input transform z = relu(dinv[i]*in[i][k] + bIn[k])  (layer-2 input)
// 128 threads -> 128 nodes x 64 cols; K in chunks of 64.
// smem/CTA = 16KB (Ws) + 32KB (Xs, TRANSPOSED [k][node], pitch 128) = 48KB
// -> 4 CTAs/SM, 16 warps. Thread (tx,ty): cols {4tx..+4, 4tx+32..+4},
// nodes 8*ty..+8. Per warp-k: 4 LDS.128 (16 wf) feed 32 FFMA2 (64 SMSP-cyc):
// crossbar demand == fma demand (ratio 1.0) -> both pipes saturate.
template <int K, bool TRANS>
__global__ void __launch_bounds__(128, 4)
gemm_kernel(const float* __restrict__ X, const float* __restrict__ W,
            const float* __restrict__ bIn,
            float* __restrict__ H, float* __restrict__ AGG, int n) {
    constexpr int KC = 64;                 // k-chunk
    constexpr int NC = K / KC;             // chunks (2 for K=128, 1 for K=64)
    __shared__ float Ws[KC * HID];         // 16KB [k][col]
    __shared__ float Xs[KC * 128];         // 32KB [k][node]
    const int t = threadIdx.x;
    const int node0 = blockIdx.x * 128;
    const int mynode = node0 + t;
    const bool ok = mynode < n;
    const float mydi = (TRANS && ok) ? g_deg[mynode] : 0.f;

    const int tx = t & 7;
    const int ty = t >> 3;                 // 0..15
    const int cA = tx * 4;                 // cols cA..+3 and cA+32..+3
    const int n0 = ty * 8;                 // nodes n0..n0+7

    unsigned long long acc[8][4];          // [node j][col pair] f32x2
#pragma unroll
    for (int j = 0; j < 8; ++j)
#pragma unroll
        for (int p = 0; p < 4; ++p) acc[j][p] = 0ULL;

#pragma unroll
    for (int c = 0; c < NC; ++c) {
        const int k0 = c * KC;
        if (c) __syncthreads();            // done reading previous chunk

        // W chunk fill: 4096 floats, 8 float4 per thread, coalesced
#pragma unroll
        for (int i = 0; i < KC * HID / 512; ++i)
            *(float4*)(Ws + i * 512 + t * 4) =
                *(const float4*)(W + k0 * HID + i * 512 + t * 4);

        // X chunk fill: thread t streams row mynode, transposes into Xs[k][t]
        // (STS at consecutive-lane addresses: conflict-free)
#pragma unroll
        for (int g = 0; g < KC / 4; ++g) {
            float4 v = make_float4(0.f, 0.f, 0.f, 0.f);
            if (ok) {
                v = *(const float4*)(X + mynode * K + k0 + g * 4);
                if (TRANS) {
                    float4 bb = *(const float4*)(bIn + k0 + g * 4);
                    v.x = fmaxf(fmaf(mydi, v.x, bb.x), 0.f);
                    v.y = fmaxf(fmaf(mydi, v.y, bb.y), 0.f);
                    v.z = fmaxf(fmaf(mydi, v.z, bb.z), 0.f);
                    v.w = fmaxf(fmaf(mydi, v.w, bb.w), 0.f);
                }
            }
            Xs[(g * 4 + 0) * 128 + t] = v.x;
            Xs[(g * 4 + 1) * 128 + t] = v.y;
            Xs[(g * 4 + 2) * 128 + t] = v.z;
            Xs[(g * 4 + 3) * 128 + t] = v.w;
        }
        __syncthreads();

        // compute chunk: per k, 4 LDS.128 + 32 FFMA2
#pragma unroll 4
        for (int k = 0; k < KC; ++k) {
            ulonglong2 wA = *(const ulonglong2*)(Ws + k * HID + cA);
            ulonglong2 wB = *(const ulonglong2*)(Ws + k * HID + cA + 32);
            float4 xa = *(const float4*)(Xs + k * 128 + n0);
            float4 xb = *(const float4*)(Xs + k * 128 + n0 + 4);
            float xs[8] = {xa.x, xa.y, xa.z, xa.w, xb.x, xb.y, xb.z, xb.w};
#pragma unroll
            for (int j = 0; j < 8; ++j) {
                unsigned long long xx;
                asm("mov.b64 %0, {%1, %1};" : "=l"(xx) : "f"(xs[j]));
                asm("fma.rn.f32x2 %0, %1, %2, %0;" : "+l"(acc[j][0]) : "l"(wA.x), "l"(xx));
                asm("fma.rn.f32x2 %0, %1, %2, %0;" : "+l"(acc[j][1]) : "l"(wA.y), "l"(xx));
                asm("fma.rn.f32x2 %0, %1, %2, %0;" : "+l"(acc[j][2]) : "l"(wB.x), "l"(xx));
                asm("fma.rn.f32x2 %0, %1, %2, %0;" : "+l"(acc[j][3]) : "l"(wB.y), "l"(xx));
            }
        }
    }

#pragma unroll
    for (int j = 0; j < 8; ++j) {
        int node = node0 + n0 + j;
        if (node < n) {
            float di = g_deg[node];
            float o[8];
            asm("mov.b64 {%0,%1}, %2;" : "=f"(o[0]), "=f"(o[1]) : "l"(acc[j][0]));
            asm("mov.b64 {%0,%1}, %2;" : "=f"(o[2]), "=f"(o[3]) : "l"(acc[j][1]));
            asm("mov.b64 {%0,%1}, %2;" : "=f"(o[4]), "=f"(o[5]) : "l"(acc[j][2]));
            asm("mov.b64 {%0,%1}, %2;" : "=f"(o[6]), "=f"(o[7]) : "l"(acc[j][3]));
            float4 r0 = make_float4(o[0] * di, o[1] * di, o[2] * di, o[3] * di);
            float4 r1 = make_float4(o[4] * di, o[5] * di, o[6] * di, o[7] * di);
            int off = node * HID + cA;
            *(float4*)(H + off) = r0;
            *(float4*)(H + off + 32) = r1;
            *(float4*)(AGG + off) = r0;    // self-loop init: agg starts at h'[node]
            *(float4*)(AGG + off + 32) = r1;
        }
    }
}

// ---------------------------------------------------------------------------
// aggregation: agg[dst] += h'[src]  (unweighted; norm folded into producer/consumer)
// 16 lanes per edge, one red.global.add.v4.f32 per lane.
__global__ void agg_kernel(const int* __restrict__ src, const int* __restrict__ dst,
                           const float* __restrict__ h, float* __restrict__ agg, int e) {
    int tid = blockIdx.x * blockDim.x + threadIdx.x;
    int edge = tid >> 4;
    int q = tid & 15;
    if (edge >= e) return;
    int s = __ldg(src + edge);
    int d = __ldg(dst + edge);
    float4 v = *(const float4*)(h + s * HID + q * 4);
    float* p = agg + d * HID + q * 4;
    asm volatile("red.global.add.v4.f32 [%0], {%1,%2,%3,%4};"
                 :: "l"(p), "f"(v.x), "f"(v.y), "f"(v.z), "f"(v.w) : "memory");
}

// ---------------------------------------------------------------------------
// decode: out[e] = dot(z[src], z[dst]), z = dinv*agg2 + b2 on the fly.
__global__ void decode_kernel(const int* __restrict__ src, const int* __restrict__ dst,
                              const float* __restrict__ agg, const float* __restrict__ b,
                              float* __restrict__ out, int e) {
    int tid = blockIdx.x * blockDim.x + threadIdx.x;
    int edge = tid >> 4;
    int q = tid & 15;
    if (edge >= e) return;
    int s = __ldg(src + edge);
    int d = __ldg(dst + edge);
    float ds = g_deg[s], dd = g_deg[d];
    float4 as = *(const float4*)(agg + s * HID + q * 4);
    float4 ad = *(const float4*)(agg + d * HID + q * 4);
    float4 bb = *(const float4*)(b + q * 4);
    float p;
    {
        float zs = fmaf(ds, as.x, bb.x), zd = fmaf(dd, ad.x, bb.x);
        p = zs * zd;
        zs = fmaf(ds, as.y, bb.y); zd = fmaf(dd, ad.y, bb.y); p = fmaf(zs, zd, p);
        zs = fmaf(ds, as.z, bb.z); zd = fmaf(dd, ad.z, bb.z); p = fmaf(zs, zd, p);
        zs = fmaf(ds, as.w, bb.w); zd = fmaf(dd, ad.w, bb.w); p = fmaf(zs, zd, p);
    }
    p += __shfl_xor_sync(0xffffffffu, p, 8);
    p += __shfl_xor_sync(0xffffffffu, p, 4);
    p += __shfl_xor_sync(0xffffffffu, p, 2);
    p += __shfl_xor_sync(0xffffffffu, p, 1);
    if (q == 0) out[edge] = p;
}

// ---------------------------------------------------------------------------
extern "C" void kernel_launch(void* const* d_in, const int* in_sizes, int n_in,
                              void* d_out, int out_size) {
    const float* x  = (const float*)d_in[0];   // [n, IN_CH]
    const int*   ei = (const int*)d_in[1];     // [2, e]
    const float* W1 = (const float*)d_in[2];
    const float* b1 = (const float*)d_in[3];
    const float* W2 = (const float*)d_in[4];
    const float* b2 = (const float*)d_in[5];
    float* out = (float*)d_out;                // [e]

    int n = in_sizes[0] / IN_CH;
    int e = in_sizes[1] / 2;
    const int* src = ei;
    const int* dst = ei + e;

    float *p_h, *p_agg1, *p_agg2;
    cudaGetSymbolAddress((void**)&p_h, g_h);
    cudaGetSymbolAddress((void**)&p_agg1, g_agg1);
    cudaGetSymbolAddress((void**)&p_agg2, g_agg2);

    const int T = 256;
    int eg = (e * 16 + T - 1) / T;             // 16 lanes per edge

    init_deg_kernel<<<(n + T - 1) / T, T>>>(n);
    degree_kernel<<<(e + T - 1) / T, T>>>(dst, e);
    dinv_kernel<<<(n + T - 1) / T, T>>>(n);

    // layer 1: h' = (X@W1)*dinv, dual-store (agg1 starts at self-loop term)
    gemm_kernel<IN_CH, false><<<(n + 127) / 128, 128>>>(x, W1, nullptr, p_h, p_agg1, n);
    agg_kernel<<<eg, T>>>(src, dst, p_h, p_agg1, e);

    // layer 2: input z1 = relu(dinv*agg1 + b1) fused into GEMM load
    gemm_kernel<HID, true><<<(n + 127) / 128, 128>>>(p_agg1, W2, b1, p_h, p_agg2, n);
    agg_kernel<<<eg, T>>>(src, dst, p_h, p_agg2, e);

    // decode (z2 = dinv*agg2 + b2 folded)
    decode_kernel<<<eg, T>>>(src, dst, p_agg2, b2, out, e);
}

// round 12
// speedup vs baseline: 1.1478x; 1.0371x over previous
#include <cuda_runtime.h>
#include <cuda_fp16.h>
#include <math.h>

#define IN_CH 128
#define HID 64
#define NMAX 50000
#define EMAX 800000

// Scratch (__device__ globals; no allocation allowed)
__device__ float   g_deg[NMAX];            // degree, then dinv in place
__device__ __half2 g_h16[NMAX * (HID / 2)];// h' fp16 (gather source, both layers)
__device__ float   g_agg1[NMAX * HID];     // layer-1 aggregation (fp32 REDs)
__device__ float   g_agg2[NMAX * HID];     // layer-2 aggregation (fp32 REDs)
__device__ __half2 g_z16[NMAX * (HID / 2)];// z2 fp16 (decode gather source)

// pack two fp32 into one 32-bit half2 payload
static __device__ __forceinline__ unsigned pack_h2(float a, float b) {
    __half2 h = __floats2half2_rn(a, b);
    return *(unsigned*)&h;
}

// ---------------------------------------------------------------------------
__global__ void init_deg_kernel(int n) {
    int i = blockIdx.x * blockDim.x + threadIdx.x;
    if (i < n) g_deg[i] = 1.0f;            // self-loop contributes 1
}

__global__ void degree_kernel(const int* __restrict__ dst, int e) {
    int i = blockIdx.x * blockDim.x + threadIdx.x;
    if (i < e) {
        float* p = &g_deg[__ldg(dst + i)];
        asm volatile("red.global.add.f32 [%0], %1;" :: "l"(p), "f"(1.0f) : "memory");
    }
}

__global__ void dinv_kernel(int n) {
    int i = blockIdx.x * blockDim.x + threadIdx.x;
    if (i < n) g_deg[i] = rsqrtf(g_deg[i]);
}

// ---------------------------------------------------------------------------
// GEMM: out[i][c] = dinv[i] * sum_k in[i][k] * W[k][c].
// Dual-store: fp16 -> H16 (edge gather source), fp32 -> AGG (self-loop init).
// TRANS: input transform z = relu(dinv[i]*in[i][k] + bIn[k])  (layer-2 input)
// 128 threads -> 128 nodes x 64 cols; K in chunks of 64 (R10-proven shape).
template <int K, bool TRANS>
__global__ void __launch_bounds__(128, 4)
gemm_kernel(const float* __restrict__ X, const float* __restrict__ W,
            const float* __restrict__ bIn,
            __half2* __restrict__ H16, float* __restrict__ AGG, int n) {
    constexpr int KC = 64;
    constexpr int NC = K / KC;
    __shared__ float Ws[KC * HID];         // 16KB [k][col]
    __shared__ float Xs[KC * 128];         // 32KB [k][node]
    const int t = threadIdx.x;
    const int node0 = blockIdx.x * 128;
    const int mynode = node0 + t;
    const bool ok = mynode < n;
    const float mydi = (TRANS && ok) ? g_deg[mynode] : 0.f;

    const int tx = t & 7;
    const int ty = t >> 3;                 // 0..15
    const int cA = tx * 4;
    const int n0 = ty * 8;

    unsigned long long acc[8][4];
#pragma unroll
    for (int j = 0; j < 8; ++j)
#pragma unroll
        for (int p = 0; p < 4; ++p) acc[j][p] = 0ULL;

#pragma unroll
    for (int c = 0; c < NC; ++c) {
        const int k0 = c * KC;
        if (c) __syncthreads();

#pragma unroll
        for (int i = 0; i < KC * HID / 512; ++i)
            *(float4*)(Ws + i * 512 + t * 4) =
                *(const float4*)(W + k0 * HID + i * 512 + t * 4);

#pragma unroll
        for (int g = 0; g < KC / 4; ++g) {
            float4 v = make_float4(0.f, 0.f, 0.f, 0.f);
            if (ok) {
                v = *(const float4*)(X + mynode * K + k0 + g * 4);
                if (TRANS) {
                    float4 bb = *(const float4*)(bIn + k0 + g * 4);
                    v.x = fmaxf(fmaf(mydi, v.x, bb.x), 0.f);
                    v.y = fmaxf(fmaf(mydi, v.y, bb.y), 0.f);
                    v.z = fmaxf(fmaf(mydi, v.z, bb.z), 0.f);
                    v.w = fmaxf(fmaf(mydi, v.w, bb.w), 0.f);
                }
            }
            Xs[(g * 4 + 0) * 128 + t] = v.x;
            Xs[(g * 4 + 1) * 128 + t] = v.y;
            Xs[(g * 4 + 2) * 128 + t] = v.z;
            Xs[(g * 4 + 3) * 128 + t] = v.w;
        }
        __syncthreads();

#pragma unroll 4
        for (int k = 0; k < KC; ++k) {
            ulonglong2 wA = *(const ulonglong2*)(Ws + k * HID + cA);
            ulonglong2 wB = *(const ulonglong2*)(Ws + k * HID + cA + 32);
            float4 xa = *(const float4*)(Xs + k * 128 + n0);
            float4 xb = *(const float4*)(Xs + k * 128 + n0 + 4);
            float xs[8] = {xa.x, xa.y, xa.z, xa.w, xb.x, xb.y, xb.z, xb.w};
#pragma unroll
            for (int j = 0; j < 8; ++j) {
                unsigned long long xx;
                asm("mov.b64 %0, {%1, %1};" : "=l"(xx) : "f"(xs[j]));
                asm("fma.rn.f32x2 %0, %1, %2, %0;" : "+l"(acc[j][0]) : "l"(wA.x), "l"(xx));
                asm("fma.rn.f32x2 %0, %1, %2, %0;" : "+l"(acc[j][1]) : "l"(wA.y), "l"(xx));
                asm("fma.rn.f32x2 %0, %1, %2, %0;" : "+l"(acc[j][2]) : "l"(wB.x), "l"(xx));
                asm("fma.rn.f32x2 %0, %1, %2, %0;" : "+l"(acc[j][3]) : "l"(wB.y), "l"(xx));
            }
        }
    }

#pragma unroll
    for (int j = 0; j < 8; ++j) {
        int node = node0 + n0 + j;
        if (node < n) {
            float di = g_deg[node];
            float o[8];
            asm("mov.b64 {%0,%1}, %2;" : "=f"(o[0]), "=f"(o[1]) : "l"(acc[j][0]));
            asm("mov.b64 {%0,%1}, %2;" : "=f"(o[2]), "=f"(o[3]) : "l"(acc[j][1]));
            asm("mov.b64 {%0,%1}, %2;" : "=f"(o[4]), "=f"(o[5]) : "l"(acc[j][2]));
            asm("mov.b64 {%0,%1}, %2;" : "=f"(o[6]), "=f"(o[7]) : "l"(acc[j][3]));
            float4 r0 = make_float4(o[0] * di, o[1] * di, o[2] * di, o[3] * di);
            float4 r1 = make_float4(o[4] * di, o[5] * di, o[6] * di, o[7] * di);
            int off = node * HID + cA;
            *(float4*)(AGG + off) = r0;        // self-loop init (fp32)
            *(float4*)(AGG + off + 32) = r1;
            // fp16 gather copy
            uint2 u0, u1;
            u0.x = pack_h2(r0.x, r0.y);
            u0.y = pack_h2(r0.z, r0.w);
            u1.x = pack_h2(r1.x, r1.y);
            u1.y = pack_h2(r1.z, r1.w);
            __half2* hp = H16 + node * (HID / 2) + cA / 2;
            *(uint2*)hp = u0;
            *(uint2*)(hp + 16) = u1;
        }
    }
}

// ---------------------------------------------------------------------------
// aggregation: agg[dst] += h'[src]; fp16 gather (8B/lane), fp32 v4 RED.
__global__ void agg_kernel(const int* __restrict__ src, const int* __restrict__ dst,
                           const __half2* __restrict__ h16, float* __restrict__ agg, int e) {
    int tid = blockIdx.x * blockDim.x + threadIdx.x;
    int edge = tid >> 4;
    int q = tid & 15;
    if (edge >= e) return;
    int s = __ldg(src + edge);
    int d = __ldg(dst + edge);
    uint2 raw = __ldg((const uint2*)(h16 + s * (HID / 2) + q * 2));
    float2 fa = __half22float2(*(__half2*)&raw.x);
    float2 fb = __half22float2(*(__half2*)&raw.y);
    float* p = agg + d * HID + q * 4;
    asm volatile("red.global.add.v4.f32 [%0], {%1,%2,%3,%4};"
                 :: "l"(p), "f"(fa.x), "f"(fa.y), "f"(fb.x), "f"(fb.y) : "memory");
}

// ---------------------------------------------------------------------------
// z2 = dinv*agg2 + b2, stored fp16 for the decode gathers.
__global__ void z2_kernel(const float* __restrict__ agg, const float* __restrict__ b, int n) {
    int i = blockIdx.x * blockDim.x + threadIdx.x;   // n*16 threads, 4 cols each
    if (i >= n * (HID / 4)) return;
    int node = i >> 4;
    int c = (i & 15) * 4;
    float di = g_deg[node];
    float4 v = *(const float4*)(agg + node * HID + c);
    float4 bb = *(const float4*)(b + c);
    uint2 u;
    u.x = pack_h2(fmaf(di, v.x, bb.x), fmaf(di, v.y, bb.y));
    u.y = pack_h2(fmaf(di, v.z, bb.z), fmaf(di, v.w, bb.w));
    *(uint2*)(g_z16 + node * (HID / 2) + c / 2) = u;
}

// ---------------------------------------------------------------------------
// decode: out[e] = dot(z16[src], z16[dst]); 16 lanes/edge, 8B gathers.
__global__ void decode_kernel(const int* __restrict__ src, const int* __restrict__ dst,
                              float* __restrict__ out, int e) {
    int tid = blockIdx.x * blockDim.x + threadIdx.x;
    int edge = tid >> 4;
    int q = tid & 15;
    if (edge >= e) return;
    int s = __ldg(src + edge);
    int d = __ldg(dst + edge);
    uint2 rs = __ldg((const uint2*)(g_z16 + s * (HID / 2) + q * 2));
    uint2 rd = __ldg((const uint2*)(g_z16 + d * (HID / 2) + q * 2));
    float2 s0 = __half22float2(*(__half2*)&rs.x);
    float2 s1 = __half22float2(*(__half2*)&rs.y);
    float2 d0 = __half22float2(*(__half2*)&rd.x);
    float2 d1 = __half22float2(*(__half2*)&rd.y);
    float p = s0.x * d0.x;
    p = fmaf(s0.y, d0.y, p);
    p = fmaf(s1.x, d1.x, p);
    p = fmaf(s1.y, d1.y, p);
    p += __shfl_xor_sync(0xffffffffu, p, 8);
    p += __shfl_xor_sync(0xffffffffu, p, 4);
    p += __shfl_xor_sync(0xffffffffu, p, 2);
    p += __shfl_xor_sync(0xffffffffu, p, 1);
    if (q == 0) out[edge] = p;
}

// ---------------------------------------------------------------------------
extern "C" void kernel_launch(void* const* d_in, const int* in_sizes, int n_in,
                              void* d_out, int out_size) {
    const float* x  = (const float*)d_in[0];   // [n, IN_CH]
    const int*   ei = (const int*)d_in[1];     // [2, e]
    const float* W1 = (const float*)d_in[2];
    const float* b1 = (const float*)d_in[3];
    const float* W2 = (const float*)d_in[4];
    const float* b2 = (const float*)d_in[5];
    float* out = (float*)d_out;                // [e]

    int n = in_sizes[0] / IN_CH;
    int e = in_sizes[1] / 2;
    const int* src = ei;
    const int* dst = ei + e;

    __half2* p_h16;
    float *p_agg1, *p_agg2;
    cudaGetSymbolAddress((void**)&p_h16, g_h16);
    cudaGetSymbolAddress((void**)&p_agg1, g_agg1);
    cudaGetSymbolAddress((void**)&p_agg2, g_agg2);

    const int T = 256;
    int eg = (e * 16 + T - 1) / T;             // 16 lanes per edge

    init_deg_kernel<<<(n + T - 1) / T, T>>>(n);
    degree_kernel<<<(e + T - 1) / T, T>>>(dst, e);
    dinv_kernel<<<(n + T - 1) / T, T>>>(n);

    // layer 1: h' = (X@W1)*dinv; fp16 to H16, fp32 self-loop init to AGG1
    gemm_kernel<IN_CH, false><<<(n + 127) / 128, 128>>>(x, W1, nullptr, p_h16, p_agg1, n);
    agg_kernel<<<eg, T>>>(src, dst, p_h16, p_agg1, e);

    // layer 2: input z1 = relu(dinv*agg1 + b1) fused into GEMM load
    gemm_kernel<HID, true><<<(n + 127) / 128, 128>>>(p_agg1, W2, b1, p_h16, p_agg2, n);
    agg_kernel<<<eg, T>>>(src, dst, p_h16, p_agg2, e);

    // z2 = dinv*agg2 + b2 (fp16), then decode from fp16
    z2_kernel<<<(n * (HID / 4) + T - 1) / T, T>>>(p_agg2, b2, n);
    decode_kernel<<<eg, T>>>(src, dst, out, e);
}

// round 13
// speedup vs baseline: 1.4820x; 1.2912x over previous
#include <cuda_runtime.h>
#include <cuda_fp16.h>
#include <math.h>

#define IN_CH 128
#define HID 64
#define NMAX 50000
#define EMAX 800000

// Scratch (__device__ globals; no allocation allowed)
__device__ float   g_deg[NMAX];               // degree, then dinv in place
__device__ __half2 g_h16[NMAX * (HID / 2)];   // h' fp16 (gather source, both layers)
__device__ __half2 g_agg1[NMAX * (HID / 2)];  // layer-1 aggregation (fp16 REDs)
__device__ __half2 g_agg2[NMAX * (HID / 2)];  // layer-2 aggregation (fp16 REDs)
__device__ __half2 g_z16[NMAX * (HID / 2)];   // z2 fp16 (decode gather source)

// pack two fp32 into one 32-bit half2 payload
static __device__ __forceinline__ unsigned pack_h2(float a, float b) {
    __half2 h = __floats2half2_rn(a, b);
    return *(unsigned*)&h;
}

// ---------------------------------------------------------------------------
__global__ void init_deg_kernel(int n) {
    int i = blockIdx.x * blockDim.x + threadIdx.x;
    if (i < n) g_deg[i] = 1.0f;               // self-loop contributes 1
}

__global__ void degree_kernel(const int* __restrict__ dst, int e) {
    int i = blockIdx.x * blockDim.x + threadIdx.x;
    if (i < e) {
        float* p = &g_deg[__ldg(dst + i)];
        asm volatile("red.global.add.f32 [%0], %1;" :: "l"(p), "f"(1.0f) : "memory");
    }
}

__global__ void dinv_kernel(int n) {
    int i = blockIdx.x * blockDim.x + threadIdx.x;
    if (i < n) g_deg[i] = rsqrtf(g_deg[i]);
}

// ---------------------------------------------------------------------------
// GEMM: out[i][c] = dinv[i] * sum_k in[i][k] * W[k][c].
// Dual-store fp16: -> H16 (edge gather source) and -> AGG16 (self-loop init).
// TRANS: input read from fp16 AGG of previous layer, z = relu(dinv*agg + bIn).
// 128 threads -> 128 nodes x 64 cols; K in chunks of 64 (R10-proven shape).
template <int K, bool TRANS>
__global__ void __launch_bounds__(128, 4)
gemm_kernel(const float* __restrict__ X, const __half2* __restrict__ X16,
            const float* __restrict__ W, const float* __restrict__ bIn,
            __half2* __restrict__ H16, __half2* __restrict__ AGG16, int n) {
    constexpr int KC = 64;
    constexpr int NC = K / KC;
    __shared__ float Ws[KC * HID];            // 16KB [k][col]
    __shared__ float Xs[KC * 128];            // 32KB [k][node]
    const int t = threadIdx.x;
    const int node0 = blockIdx.x * 128;
    const int mynode = node0 + t;
    const bool ok = mynode < n;
    const float mydi = (TRANS && ok) ? g_deg[mynode] : 0.f;

    const int tx = t & 7;
    const int ty = t >> 3;                    // 0..15
    const int cA = tx * 4;
    const int n0 = ty * 8;

    unsigned long long acc[8][4];
#pragma unroll
    for (int j = 0; j < 8; ++j)
#pragma unroll
        for (int p = 0; p < 4; ++p) acc[j][p] = 0ULL;

#pragma unroll
    for (int c = 0; c < NC; ++c) {
        const int k0 = c * KC;
        if (c) __syncthreads();

#pragma unroll
        for (int i = 0; i < KC * HID / 512; ++i)
            *(float4*)(Ws + i * 512 + t * 4) =
                *(const float4*)(W + k0 * HID + i * 512 + t * 4);

#pragma unroll
        for (int g = 0; g < KC / 4; ++g) {
            float4 v = make_float4(0.f, 0.f, 0.f, 0.f);
            if (ok) {
                if (TRANS) {
                    // read 4 cols from fp16 agg of previous layer
                    uint2 r = *(const uint2*)(X16 + mynode * (HID / 2) + (k0 + g * 4) / 2);
                    float2 f0 = __half22float2(*(__half2*)&r.x);
                    float2 f1 = __half22float2(*(__half2*)&r.y);
                    float4 bb = *(const float4*)(bIn + k0 + g * 4);
                    v.x = fmaxf(fmaf(mydi, f0.x, bb.x), 0.f);
                    v.y = fmaxf(fmaf(mydi, f0.y, bb.y), 0.f);
                    v.z = fmaxf(fmaf(mydi, f1.x, bb.z), 0.f);
                    v.w = fmaxf(fmaf(mydi, f1.y, bb.w), 0.f);
                } else {
                    v = *(const float4*)(X + mynode * K + k0 + g * 4);
                }
            }
            Xs[(g * 4 + 0) * 128 + t] = v.x;
            Xs[(g * 4 + 1) * 128 + t] = v.y;
            Xs[(g * 4 + 2) * 128 + t] = v.z;
            Xs[(g * 4 + 3) * 128 + t] = v.w;
        }
        __syncthreads();

#pragma unroll 4
        for (int k = 0; k < KC; ++k) {
            ulonglong2 wA = *(const ulonglong2*)(Ws + k * HID + cA);
            ulonglong2 wB = *(const ulonglong2*)(Ws + k * HID + cA + 32);
            float4 xa = *(const float4*)(Xs + k * 128 + n0);
            float4 xb = *(const float4*)(Xs + k * 128 + n0 + 4);
            float xs[8] = {xa.x, xa.y, xa.z, xa.w, xb.x, xb.y, xb.z, xb.w};
#pragma unroll
            for (int j = 0; j < 8; ++j) {
                unsigned long long xx;
                asm("mov.b64 %0, {%1, %1};" : "=l"(xx) : "f"(xs[j]));
                asm("fma.rn.f32x2 %0, %1, %2, %0;" : "+l"(acc[j][0]) : "l"(wA.x), "l"(xx));
                asm("fma.rn.f32x2 %0, %1, %2, %0;" : "+l"(acc[j][1]) : "l"(wA.y), "l"(xx));
                asm("fma.rn.f32x2 %0, %1, %2, %0;" : "+l"(acc[j][2]) : "l"(wB.x), "l"(xx));
                asm("fma.rn.f32x2 %0, %1, %2, %0;" : "+l"(acc[j][3]) : "l"(wB.y), "l"(xx));
            }
        }
    }

#pragma unroll
    for (int j = 0; j < 8; ++j) {
        int node = node0 + n0 + j;
        if (node < n) {
            float di = g_deg[node];
            float o[8];
            asm("mov.b64 {%0,%1}, %2;" : "=f"(o[0]), "=f"(o[1]) : "l"(acc[j][0]));
            asm("mov.b64 {%0,%1}, %2;" : "=f"(o[2]), "=f"(o[3]) : "l"(acc[j][1]));
            asm("mov.b64 {%0,%1}, %2;" : "=f"(o[4]), "=f"(o[5]) : "l"(acc[j][2]));
            asm("mov.b64 {%0,%1}, %2;" : "=f"(o[6]), "=f"(o[7]) : "l"(acc[j][3]));
            uint2 u0, u1;
            u0.x = pack_h2(o[0] * di, o[1] * di);
            u0.y = pack_h2(o[2] * di, o[3] * di);
            u1.x = pack_h2(o[4] * di, o[5] * di);
            u1.y = pack_h2(o[6] * di, o[7] * di);
            __half2* hp = H16 + node * (HID / 2) + cA / 2;
            __half2* ap = AGG16 + node * (HID / 2) + cA / 2;
            *(uint2*)hp = u0;
            *(uint2*)(hp + 16) = u1;          // +32 cols
            *(uint2*)ap = u0;                 // self-loop init
            *(uint2*)(ap + 16) = u1;
        }
    }
}

// ---------------------------------------------------------------------------
// aggregation: agg[dst] += h'[src]; fp16 all the way.
// 8 lanes per edge; each lane: one uint4 gather (8 halves) + one v4.f16x2 RED.
__global__ void agg_kernel(const int* __restrict__ src, const int* __restrict__ dst,
                           const __half2* __restrict__ h16, __half2* __restrict__ agg, int e) {
    int tid = blockIdx.x * blockDim.x + threadIdx.x;
    int edge = tid >> 3;
    int q = tid & 7;
    if (edge >= e) return;
    int s = __ldg(src + edge);
    int d = __ldg(dst + edge);
    uint4 raw = __ldg((const uint4*)(h16 + s * (HID / 2) + q * 4));
    __half2* p = agg + d * (HID / 2) + q * 4;
    asm volatile("red.global.add.noftz.v4.f16x2 [%0], {%1,%2,%3,%4};"
                 :: "l"(p), "r"(raw.x), "r"(raw.y), "r"(raw.z), "r"(raw.w) : "memory");
}

// ---------------------------------------------------------------------------
// z2 = dinv*agg2 + b2, stored fp16 for the decode gathers.
__global__ void z2_kernel(const float* __restrict__ b, int n) {
    int i = blockIdx.x * blockDim.x + threadIdx.x;   // n*16 threads, 4 cols each
    if (i >= n * (HID / 4)) return;
    int node = i >> 4;
    int c = (i & 15) * 4;
    float di = g_deg[node];
    uint2 r = *(const uint2*)(g_agg2 + node * (HID / 2) + c / 2);
    float2 f0 = __half22float2(*(__half2*)&r.x);
    float2 f1 = __half22float2(*(__half2*)&r.y);
    float4 bb = *(const float4*)(b + c);
    uint2 u;
    u.x = pack_h2(fmaf(di, f0.x, bb.x), fmaf(di, f0.y, bb.y));
    u.y = pack_h2(fmaf(di, f1.x, bb.z), fmaf(di, f1.y, bb.w));
    *(uint2*)(g_z16 + node * (HID / 2) + c / 2) = u;
}

// ---------------------------------------------------------------------------
// decode: out[e] = dot(z16[src], z16[dst]); 16 lanes/edge, 8B gathers.
__global__ void decode_kernel(const int* __restrict__ src, const int* __restrict__ dst,
                              float* __restrict__ out, int e) {
    int tid = blockIdx.x * blockDim.x + threadIdx.x;
    int edge = tid >> 4;
    int q = tid & 15;
    if (edge >= e) return;
    int s = __ldg(src + edge);
    int d = __ldg(dst + edge);
    uint2 rs = __ldg((const uint2*)(g_z16 + s * (HID / 2) + q * 2));
    uint2 rd = __ldg((const uint2*)(g_z16 + d * (HID / 2) + q * 2));
    float2 s0 = __half22float2(*(__half2*)&rs.x);
    float2 s1 = __half22float2(*(__half2*)&rs.y);
    float2 d0 = __half22float2(*(__half2*)&rd.x);
    float2 d1 = __half22float2(*(__half2*)&rd.y);
    float p = s0.x * d0.x;
    p = fmaf(s0.y, d0.y, p);
    p = fmaf(s1.x, d1.x, p);
    p = fmaf(s1.y, d1.y, p);
    p += __shfl_xor_sync(0xffffffffu, p, 8);
    p += __shfl_xor_sync(0xffffffffu, p, 4);
    p += __shfl_xor_sync(0xffffffffu, p, 2);
    p += __shfl_xor_sync(0xffffffffu, p, 1);
    if (q == 0) out[edge] = p;
}

// ---------------------------------------------------------------------------
extern "C" void kernel_launch(void* const* d_in, const int* in_sizes, int n_in,
                              void* d_out, int out_size) {
    const float* x  = (const float*)d_in[0];   // [n, IN_CH]
    const int*   ei = (const int*)d_in[1];     // [2, e]
    const float* W1 = (const float*)d_in[2];
    const float* b1 = (const float*)d_in[3];
    const float* W2 = (const float*)d_in[4];
    const float* b2 = (const float*)d_in[5];
    float* out = (float*)d_out;                // [e]

    int n = in_sizes[0] / IN_CH;
    int e = in_sizes[1] / 2;
    const int* src = ei;
    const int* dst = ei + e;

    __half2 *p_h16, *p_agg1, *p_agg2;
    cudaGetSymbolAddress((void**)&p_h16, g_h16);
    cudaGetSymbolAddress((void**)&p_agg1, g_agg1);
    cudaGetSymbolAddress((void**)&p_agg2, g_agg2);

    const int T = 256;
    int eg8  = (e * 8 + T - 1) / T;            // 8 lanes per edge (agg)
    int eg16 = (e * 16 + T - 1) / T;           // 16 lanes per edge (decode)

    init_deg_kernel<<<(n + T - 1) / T, T>>>(n);
    degree_kernel<<<(e + T - 1) / T, T>>>(dst, e);
    dinv_kernel<<<(n + T - 1) / T, T>>>(n);

    // layer 1: h' = (X@W1)*dinv; fp16 to H16 + AGG1 (self-loop init)
    gemm_kernel<IN_CH, false><<<(n + 127) / 128, 128>>>(x, nullptr, W1, nullptr,
                                                        p_h16, p_agg1, n);
    agg_kernel<<<eg8, T>>>(src, dst, p_h16, p_agg1, e);

    // layer 2: input z1 = relu(dinv*agg1 + b1) read from fp16 agg1
    gemm_kernel<HID, true><<<(n + 127) / 128, 128>>>(nullptr, p_agg1, W2, b1,
                                                     p_h16, p_agg2, n);
    agg_kernel<<<eg8, T>>>(src, dst, p_h16, p_agg2, e);

    // z2 = dinv*agg2 + b2 (fp16), then decode from fp16
    z2_kernel<<<(n * (HID / 4) + T - 1) / T, T>>>(b2, n);
    decode_kernel<<<eg16, T>>>(src, dst, out, e);
}

// round 14
// speedup vs baseline: 1.5843x; 1.0690x over previous
#include <cuda_runtime.h>
#include <cuda_fp16.h>
#include <math.h>

#define IN_CH 128
#define HID 64
#define NMAX 50000
#define EMAX 800000

// Scratch (__device__ globals; no allocation allowed)
__device__ float   g_deg[NMAX];               // degree (raw; consumers rsqrt)
__device__ __half2 g_h16[NMAX * (HID / 2)];   // h' fp16 (gather source, both layers)
__device__ __half2 g_agg1[NMAX * (HID / 2)];  // layer-1 aggregation (fp16 REDs)
__device__ __half2 g_agg2[NMAX * (HID / 2)];  // layer-2 aggregation (fp16 REDs)

// pack two fp32 into one 32-bit half2 payload
static __device__ __forceinline__ unsigned pack_h2(float a, float b) {
    __half2 h = __floats2half2_rn(a, b);
    return *(unsigned*)&h;
}

// ---------------------------------------------------------------------------
__global__ void init_deg_kernel(int n) {
    int i = blockIdx.x * blockDim.x + threadIdx.x;
    if (i < n) g_deg[i] = 1.0f;               // self-loop contributes 1
}

__global__ void degree_kernel(const int* __restrict__ dst, int e) {
    int i = blockIdx.x * blockDim.x + threadIdx.x;
    if (i < e) {
        float* p = &g_deg[__ldg(dst + i)];
        asm volatile("red.global.add.f32 [%0], %1;" :: "l"(p), "f"(1.0f) : "memory");
    }
}

// ---------------------------------------------------------------------------
// GEMM: out[i][c] = dinv[i] * sum_k in[i][k] * W[k][c],  dinv = rsqrt(deg) inline.
// Dual-store fp16: -> H16 (edge gather source) and -> AGG16 (self-loop init).
// TRANS: input read from fp16 AGG of previous layer, z = relu(dinv*agg + bIn).
// 128 threads -> 128 nodes x 64 cols; K in chunks of 64 (R10-proven shape).
template <int K, bool TRANS>
__global__ void __launch_bounds__(128, 4)
gemm_kernel(const float* __restrict__ X, const __half2* __restrict__ X16,
            const float* __restrict__ W, const float* __restrict__ bIn,
            __half2* __restrict__ H16, __half2* __restrict__ AGG16, int n) {
    constexpr int KC = 64;
    constexpr int NC = K / KC;
    __shared__ float Ws[KC * HID];            // 16KB [k][col]
    __shared__ float Xs[KC * 128];            // 32KB [k][node]
    const int t = threadIdx.x;
    const int node0 = blockIdx.x * 128;
    const int mynode = node0 + t;
    const bool ok = mynode < n;
    const float mydi = (TRANS && ok) ? rsqrtf(g_deg[mynode]) : 0.f;

    const int tx = t & 7;
    const int ty = t >> 3;                    // 0..15
    const int cA = tx * 4;
    const int n0 = ty * 8;

    unsigned long long acc[8][4];
#pragma unroll
    for (int j = 0; j < 8; ++j)
#pragma unroll
        for (int p = 0; p < 4; ++p) acc[j][p] = 0ULL;

#pragma unroll
    for (int c = 0; c < NC; ++c) {
        const int k0 = c * KC;
        if (c) __syncthreads();

#pragma unroll
        for (int i = 0; i < KC * HID / 512; ++i)
            *(float4*)(Ws + i * 512 + t * 4) =
                *(const float4*)(W + k0 * HID + i * 512 + t * 4);

#pragma unroll
        for (int g = 0; g < KC / 4; ++g) {
            float4 v = make_float4(0.f, 0.f, 0.f, 0.f);
            if (ok) {
                if (TRANS) {
                    uint2 r = *(const uint2*)(X16 + mynode * (HID / 2) + (k0 + g * 4) / 2);
                    float2 f0 = __half22float2(*(__half2*)&r.x);
                    float2 f1 = __half22float2(*(__half2*)&r.y);
                    float4 bb = *(const float4*)(bIn + k0 + g * 4);
                    v.x = fmaxf(fmaf(mydi, f0.x, bb.x), 0.f);
                    v.y = fmaxf(fmaf(mydi, f0.y, bb.y), 0.f);
                    v.z = fmaxf(fmaf(mydi, f1.x, bb.z), 0.f);
                    v.w = fmaxf(fmaf(mydi, f1.y, bb.w), 0.f);
                } else {
                    v = *(const float4*)(X + mynode * K + k0 + g * 4);
                }
            }
            Xs[(g * 4 + 0) * 128 + t] = v.x;
            Xs[(g * 4 + 1) * 128 + t] = v.y;
            Xs[(g * 4 + 2) * 128 + t] = v.z;
            Xs[(g * 4 + 3) * 128 + t] = v.w;
        }
        __syncthreads();

#pragma unroll 4
        for (int k = 0; k < KC; ++k) {
            ulonglong2 wA = *(const ulonglong2*)(Ws + k * HID + cA);
            ulonglong2 wB = *(const ulonglong2*)(Ws + k * HID + cA + 32);
            float4 xa = *(const float4*)(Xs + k * 128 + n0);
            float4 xb = *(const float4*)(Xs + k * 128 + n0 + 4);
            float xs[8] = {xa.x, xa.y, xa.z, xa.w, xb.x, xb.y, xb.z, xb.w};
#pragma unroll
            for (int j = 0; j < 8; ++j) {
                unsigned long long xx;
                asm("mov.b64 %0, {%1, %1};" : "=l"(xx) : "f"(xs[j]));
                asm("fma.rn.f32x2 %0, %1, %2, %0;" : "+l"(acc[j][0]) : "l"(wA.x), "l"(xx));
                asm("fma.rn.f32x2 %0, %1, %2, %0;" : "+l"(acc[j][1]) : "l"(wA.y), "l"(xx));
                asm("fma.rn.f32x2 %0, %1, %2, %0;" : "+l"(acc[j][2]) : "l"(wB.x), "l"(xx));
                asm("fma.rn.f32x2 %0, %1, %2, %0;" : "+l"(acc[j][3]) : "l"(wB.y), "l"(xx));
            }
        }
    }

#pragma unroll
    for (int j = 0; j < 8; ++j) {
        int node = node0 + n0 + j;
        if (node < n) {
            float di = rsqrtf(g_deg[node]);
            float o[8];
            asm("mov.b64 {%0,%1}, %2;" : "=f"(o[0]), "=f"(o[1]) : "l"(acc[j][0]));
            asm("mov.b64 {%0,%1}, %2;" : "=f"(o[2]), "=f"(o[3]) : "l"(acc[j][1]));
            asm("mov.b64 {%0,%1}, %2;" : "=f"(o[4]), "=f"(o[5]) : "l"(acc[j][2]));
            asm("mov.b64 {%0,%1}, %2;" : "=f"(o[6]), "=f"(o[7]) : "l"(acc[j][3]));
            uint2 u0, u1;
            u0.x = pack_h2(o[0] * di, o[1] * di);
            u0.y = pack_h2(o[2] * di, o[3] * di);
            u1.x = pack_h2(o[4] * di, o[5] * di);
            u1.y = pack_h2(o[6] * di, o[7] * di);
            __half2* hp = H16 + node * (HID / 2) + cA / 2;
            __half2* ap = AGG16 + node * (HID / 2) + cA / 2;
            *(uint2*)hp = u0;
            *(uint2*)(hp + 16) = u1;          // +32 cols
            *(uint2*)ap = u0;                 // self-loop init
            *(uint2*)(ap + 16) = u1;
        }
    }
}

// ---------------------------------------------------------------------------
// aggregation: agg[dst] += h'[src]; fp16 all the way.
// 8 lanes per edge; each lane: one uint4 gather (8 halves) + one v4.f16x2 RED.
__global__ void agg_kernel(const int* __restrict__ src, const int* __restrict__ dst,
                           const __half2* __restrict__ h16, __half2* __restrict__ agg, int e) {
    int tid = blockIdx.x * blockDim.x + threadIdx.x;
    int edge = tid >> 3;
    int q = tid & 7;
    if (edge >= e) return;
    int s = __ldg(src + edge);
    int d = __ldg(dst + edge);
    uint4 raw = __ldg((const uint4*)(h16 + s * (HID / 2) + q * 4));
    __half2* p = agg + d * (HID / 2) + q * 4;
    asm volatile("red.global.add.noftz.v4.f16x2 [%0], {%1,%2,%3,%4};"
                 :: "l"(p), "r"(raw.x), "r"(raw.y), "r"(raw.z), "r"(raw.w) : "memory");
}

// ---------------------------------------------------------------------------
// decode: out[e] = dot(z[src], z[dst]), z = rsqrt(deg)*agg2 + b2 inline.
// 8 lanes per edge; each lane gathers 8 halves (uint4) per endpoint.
__global__ void decode_kernel(const int* __restrict__ src, const int* __restrict__ dst,
                              const __half2* __restrict__ agg,
                              const float* __restrict__ b,
                              float* __restrict__ out, int e) {
    int tid = blockIdx.x * blockDim.x + threadIdx.x;
    int edge = tid >> 3;
    int q = tid & 7;
    if (edge >= e) return;
    int s = __ldg(src + edge);
    int d = __ldg(dst + edge);
    float ds = rsqrtf(g_deg[s]);
    float dd = rsqrtf(g_deg[d]);
    uint4 rs = __ldg((const uint4*)(agg + s * (HID / 2) + q * 4));
    uint4 rd = __ldg((const uint4*)(agg + d * (HID / 2) + q * 4));
    float4 b0 = *(const float4*)(b + q * 8);
    float4 b1 = *(const float4*)(b + q * 8 + 4);
    float p = 0.f;
    {
        float2 fs, fd;
        fs = __half22float2(*(__half2*)&rs.x); fd = __half22float2(*(__half2*)&rd.x);
        p = fmaf(fmaf(ds, fs.x, b0.x), fmaf(dd, fd.x, b0.x), p);
        p = fmaf(fmaf(ds, fs.y, b0.y), fmaf(dd, fd.y, b0.y), p);
        fs = __half22float2(*(__half2*)&rs.y); fd = __half22float2(*(__half2*)&rd.y);
        p = fmaf(fmaf(ds, fs.x, b0.z), fmaf(dd, fd.x, b0.z), p);
        p = fmaf(fmaf(ds, fs.y, b0.w), fmaf(dd, fd.y, b0.w), p);
        fs = __half22float2(*(__half2*)&rs.z); fd = __half22float2(*(__half2*)&rd.z);
        p = fmaf(fmaf(ds, fs.x, b1.x), fmaf(dd, fd.x, b1.x), p);
        p = fmaf(fmaf(ds, fs.y, b1.y), fmaf(dd, fd.y, b1.y), p);
        fs = __half22float2(*(__half2*)&rs.w); fd = __half22float2(*(__half2*)&rd.w);
        p = fmaf(fmaf(ds, fs.x, b1.z), fmaf(dd, fd.x, b1.z), p);
        p = fmaf(fmaf(ds, fs.y, b1.w), fmaf(dd, fd.y, b1.w), p);
    }
    p += __shfl_xor_sync(0xffffffffu, p, 4);
    p += __shfl_xor_sync(0xffffffffu, p, 2);
    p += __shfl_xor_sync(0xffffffffu, p, 1);
    if (q == 0) out[edge] = p;
}

// ---------------------------------------------------------------------------
extern "C" void kernel_launch(void* const* d_in, const int* in_sizes, int n_in,
                              void* d_out, int out_size) {
    const float* x  = (const float*)d_in[0];   // [n, IN_CH]
    const int*   ei = (const int*)d_in[1];     // [2, e]
    const float* W1 = (const float*)d_in[2];
    const float* b1 = (const float*)d_in[3];
    const float* W2 = (const float*)d_in[4];
    const float* b2 = (const float*)d_in[5];
    float* out = (float*)d_out;                // [e]

    int n = in_sizes[0] / IN_CH;
    int e = in_sizes[1] / 2;
    const int* src = ei;
    const int* dst = ei + e;

    __half2 *p_h16, *p_agg1, *p_agg2;
    cudaGetSymbolAddress((void**)&p_h16, g_h16);
    cudaGetSymbolAddress((void**)&p_agg1, g_agg1);
    cudaGetSymbolAddress((void**)&p_agg2, g_agg2);

    const int T = 256;
    int eg8 = (e * 8 + T - 1) / T;             // 8 lanes per edge

    init_deg_kernel<<<(n + T - 1) / T, T>>>(n);
    degree_kernel<<<(e + T - 1) / T, T>>>(dst, e);

    // layer 1: h' = (X@W1)*dinv; fp16 to H16 + AGG1 (self-loop init)
    gemm_kernel<IN_CH, false><<<(n + 127) / 128, 128>>>(x, nullptr, W1, nullptr,
                                                        p_h16, p_agg1, n);
    agg_kernel<<<eg8, T>>>(src, dst, p_h16, p_agg1, e);

    // layer 2: input z1 = relu(dinv*agg1 + b1) read from fp16 agg1
    gemm_kernel<HID, true><<<(n + 127) / 128, 128>>>(nullptr, p_agg1, W2, b1,
                                                     p_h16, p_agg2, n);
    agg_kernel<<<eg8, T>>>(src, dst, p_h16, p_agg2, e);

    // decode straight from fp16 agg2 (z2 = dinv*agg2 + b2 inline)
    decode_kernel<<<eg8, T>>>(src, dst, p_agg2, b2, out, e);
}